// round 15
// baseline (speedup 1.0000x reference)
#include <cuda_runtime.h>
#include <cstdint>

#define E_TOT  (256*4096)
#define NNODE  (256*512)
#define DHID   64
#define BNUM   256
#define EPB    4096
#define NPB    512
#define KKEEP  1024
#define KDROP  3072
#define NGRP   4
#define BPG    (BNUM / NGRP)     // 64 batches per group

// chunk-major AB: [batch][chunk 0..127][node 0..511] float4
__device__ float g_AB[(size_t)BNUM * 128 * 512 * 4];
__device__ float g_scores[E_TOT];

// ---- streams/events for pipelined capture (created before mem tracking) ----
static cudaStream_t sA, sB, sC;
static cudaEvent_t evA[NGRP], evB[NGRP], evOrigin, evLast;
static bool init_streams() {
    cudaStreamCreateWithFlags(&sA, cudaStreamNonBlocking);
    cudaStreamCreateWithFlags(&sB, cudaStreamNonBlocking);
    cudaStreamCreateWithFlags(&sC, cudaStreamNonBlocking);
    for (int i = 0; i < NGRP; ++i) {
        cudaEventCreateWithFlags(&evA[i], cudaEventDisableTiming);
        cudaEventCreateWithFlags(&evB[i], cudaEventDisableTiming);
    }
    cudaEventCreateWithFlags(&evOrigin, cudaEventDisableTiming);
    cudaEventCreateWithFlags(&evLast, cudaEventDisableTiming);
    return true;
}
static bool s_inited = init_streams();

__device__ __forceinline__ unsigned long long pk2(float x, float y) {
    unsigned long long r;
    asm("mov.b64 %0, {%1, %2};" : "=l"(r) : "f"(x), "f"(y));
    return r;
}
__device__ __forceinline__ void fma2(unsigned long long& d,
                                     unsigned long long a, unsigned long long b) {
    asm("fma.rn.f32x2 %0, %1, %2, %0;" : "+l"(d) : "l"(a), "l"(b));
}
__device__ __forceinline__ void cp16(unsigned int s, const void* g) {
    asm volatile("cp.async.cg.shared.global [%0], [%1], 16;" :: "r"(s), "l"(g));
}

// ---------------------------------------------------------------------------
// K1: AB = h @ Wc (R7 core, b1 folded in epilogue). tofs = tile offset.
// ---------------------------------------------------------------------------
__global__ void __launch_bounds__(256, 2) k1_gemm(const float* __restrict__ hmat,
                                                  const float* __restrict__ W1,
                                                  const float* __restrict__ b1,
                                                  int tofs) {
    extern __shared__ float sm1[];
    __shared__ float b1s[256];
    float* Ws = sm1;              // [64][256]
    float* hs = sm1 + 64 * 256;   // [64][68]
    const int tid  = threadIdx.x;
    const int tile = (blockIdx.x >> 1) + tofs;
    const int half = blockIdx.x & 1;
    const int rowbase = tile * 64;
    const int b     = rowbase >> 9;
    const int nboff = rowbase & 511;

    if (tid < 64) *(float4*)(b1s + tid * 4) = *(const float4*)(b1 + tid * 4);
    #pragma unroll
    for (int j = 0; j < 16; ++j) {
        int i = tid + j * 256;
        int k = i >> 6, o4 = i & 63;
        *(float4*)(Ws + k * 256 + o4 * 4) =
            *(const float4*)(W1 + (size_t)(half * 64 + k) * 256 + o4 * 4);
    }
    #pragma unroll
    for (int j = 0; j < 4; ++j) {
        int i = tid + j * 256;
        int n = i >> 4, k4 = i & 15;
        float4 v = *(const float4*)(hmat + (size_t)(rowbase + n) * 64 + k4 * 4);
        hs[(k4 * 4 + 0) * 68 + n] = v.x;
        hs[(k4 * 4 + 1) * 68 + n] = v.y;
        hs[(k4 * 4 + 2) * 68 + n] = v.z;
        hs[(k4 * 4 + 3) * 68 + n] = v.w;
    }
    __syncthreads();

    const int w = tid >> 5, l = tid & 31;
    const int r0 = w * 8;

    unsigned long long acc[8][4];
    #pragma unroll
    for (int i = 0; i < 8; ++i)
        #pragma unroll
        for (int p = 0; p < 4; ++p) acc[i][p] = 0ull;

    #pragma unroll 4
    for (int k = 0; k < 64; ++k) {
        float4 h0 = *(const float4*)(hs + k * 68 + r0);
        float4 h1 = *(const float4*)(hs + k * 68 + r0 + 4);
        ulonglong2 w0 = *(const ulonglong2*)(Ws + k * 256 + 4 * l);
        ulonglong2 w1 = *(const ulonglong2*)(Ws + k * 256 + 128 + 4 * l);
        float hv[8] = {h0.x, h0.y, h0.z, h0.w, h1.x, h1.y, h1.z, h1.w};
        #pragma unroll
        for (int i = 0; i < 8; ++i) {
            unsigned long long a2 = pk2(hv[i], hv[i]);
            fma2(acc[i][0], a2, w0.x); fma2(acc[i][1], a2, w0.y);
            fma2(acc[i][2], a2, w1.x); fma2(acc[i][3], a2, w1.y);
        }
    }

    __syncthreads();
    float4* st = (float4*)sm1;
    #pragma unroll
    for (int i = 0; i < 8; ++i) {
        int node = r0 + i;
        float4 v0, v1;
        *(unsigned long long*)&v0.x = acc[i][0];
        *(unsigned long long*)&v0.z = acc[i][1];
        *(unsigned long long*)&v1.x = acc[i][2];
        *(unsigned long long*)&v1.z = acc[i][3];
        st[l * 65 + node]        = v0;
        st[(32 + l) * 65 + node] = v1;
    }
    __syncthreads();
    float4* dst = (float4*)g_AB;
    if (half == 0) {
        #pragma unroll
        for (int j = 0; j < 16; ++j) {
            int idx = tid + j * 256;
            int cc = idx >> 6, node = idx & 63;
            float4 v = st[cc * 65 + node];
            float4 bv = *(const float4*)(b1s + cc * 4);
            v.x += bv.x; v.y += bv.y; v.z += bv.z; v.w += bv.w;
            dst[((size_t)b * 128 + cc) * 512 + nboff + node] = v;
        }
    } else {
        #pragma unroll
        for (int j = 0; j < 16; ++j) {
            int idx = tid + j * 256;
            int cc = idx >> 6, node = idx & 63;
            dst[((size_t)b * 128 + 64 + cc) * 512 + nboff + node] = st[cc * 65 + node];
        }
    }
}

// ---------------------------------------------------------------------------
// K2: edge scores, ONE CTA per batch (R14 version). bofs = batch offset.
// ---------------------------------------------------------------------------
__global__ void __launch_bounds__(512, 2) k2_edges(const float* __restrict__ W2,
                                                   const float* __restrict__ b2p,
                                                   const int*   __restrict__ ei,
                                                   int bofs) {
    extern __shared__ float sm2[];
    float* stage = sm2;                 // [4 bufs][2 sides][2048] = 64 KB
    float* w2s   = sm2 + 4 * 2 * 2048;  // [256]
    int* scnt  = (int*)sm2;             // [512]
    int* wsumS = (int*)sm2 + 512;       // [16]
    int* ssrow = (int*)sm2 + 544;       // [4096]
    int* sscol = ssrow + 4096;
    int* ssid  = sscol + 4096;

    const int tid = threadIdx.x;
    const int b   = blockIdx.x + bofs;
    const int ebase = b * EPB;

    scnt[tid] = 0;
    __syncthreads();
    int r8l[8], c8l[8];
    #pragma unroll
    for (int i = 0; i < 8; ++i) {
        int j = tid + i * 512;
        r8l[i] = ei[ebase + j]         - b * NPB;
        c8l[i] = ei[E_TOT + ebase + j] - b * NPB;
        atomicAdd(&scnt[r8l[i]], 1);
    }
    __syncthreads();
    {
        const int lane = tid & 31, wd = tid >> 5;
        int v = scnt[tid];
        int x = v;
        #pragma unroll
        for (int o = 1; o < 32; o <<= 1) {
            int y = __shfl_up_sync(0xffffffffu, x, o);
            if (lane >= o) x += y;
        }
        if (lane == 31) wsumS[wd] = x;
        __syncthreads();
        if (tid < 16) {
            int y = wsumS[tid], z = y;
            #pragma unroll
            for (int o = 1; o < 16; o <<= 1) {
                int t = __shfl_up_sync(0xffffu, z, o);
                if (tid >= o) z += t;
            }
            wsumS[tid] = z - y;
        }
        __syncthreads();
        int excl = x - v + wsumS[wd];
        __syncthreads();
        scnt[tid] = excl;
        __syncthreads();
    }
    #pragma unroll
    for (int i = 0; i < 8; ++i) {
        int p = atomicAdd(&scnt[r8l[i]], 1);
        ssrow[p] = r8l[i];
        sscol[p] = c8l[i];
        ssid [p] = tid + i * 512;
    }
    __syncthreads();
    int ro[8], co[8], id8[8];
    {
        int4 ra = *(const int4*)(ssrow + tid * 8);
        int4 rb = *(const int4*)(ssrow + tid * 8 + 4);
        int4 ca = *(const int4*)(sscol + tid * 8);
        int4 cb = *(const int4*)(sscol + tid * 8 + 4);
        int4 ia = *(const int4*)(ssid + tid * 8);
        int4 ib = *(const int4*)(ssid + tid * 8 + 4);
        ro[0]=ra.x*4; ro[1]=ra.y*4; ro[2]=ra.z*4; ro[3]=ra.w*4;
        ro[4]=rb.x*4; ro[5]=rb.y*4; ro[6]=rb.z*4; ro[7]=rb.w*4;
        co[0]=ca.x*4; co[1]=ca.y*4; co[2]=ca.z*4; co[3]=ca.w*4;
        co[4]=cb.x*4; co[5]=cb.y*4; co[6]=cb.z*4; co[7]=cb.w*4;
        id8[0]=ia.x; id8[1]=ia.y; id8[2]=ia.z; id8[3]=ia.w;
        id8[4]=ib.x; id8[5]=ib.y; id8[6]=ib.z; id8[7]=ib.w;
    }
    __syncthreads();
    if (tid < 64) *(float4*)(w2s + tid * 4) = *(const float4*)(W2 + tid * 4);
    __syncthreads();

    float a8[8];
    #pragma unroll
    for (int i = 0; i < 8; ++i) a8[i] = 0.f;

    const float4* gA = (const float4*)g_AB + (size_t)b * 128 * 512;
    const unsigned int sb32 =
        (unsigned int)__cvta_generic_to_shared(stage) + tid * 16;

    #pragma unroll
    for (int p = 0; p < 3; ++p) {
        cp16(sb32 + (p * 2)     * 2048 * 4, gA + (size_t)p        * 512 + tid);
        cp16(sb32 + (p * 2 + 1) * 2048 * 4, gA + (size_t)(64 + p) * 512 + tid);
        asm volatile("cp.async.commit_group;");
    }

    for (int c = 0; c < 64; ++c) {
        if (c < 62)       asm volatile("cp.async.wait_group 2;");
        else if (c == 62) asm volatile("cp.async.wait_group 1;");
        else              asm volatile("cp.async.wait_group 0;");
        __syncthreads();

        const int nc = c + 3;
        if (nc < 64) {
            const int nb = nc & 3;
            cp16(sb32 + (nb * 2)     * 2048 * 4, gA + (size_t)nc        * 512 + tid);
            cp16(sb32 + (nb * 2 + 1) * 2048 * 4, gA + (size_t)(64 + nc) * 512 + tid);
            asm volatile("cp.async.commit_group;");
        }

        const int buf = c & 3;
        const float* A0 = stage + (buf * 2) * 2048;
        const float* B0 = stage + (buf * 2 + 1) * 2048;
        const float4 w2v = *(const float4*)(w2s + c * 4);

        float4 av = *(const float4*)(A0 + ro[0]);
        #pragma unroll
        for (int i = 0; i < 8; ++i) {
            if (i > 0 && ro[i] != ro[i - 1]) av = *(const float4*)(A0 + ro[i]);
            float4 bv = *(const float4*)(B0 + co[i]);
            float s = a8[i];
            s = fmaf(fmaxf(av.x + bv.x, 0.f), w2v.x, s);
            s = fmaf(fmaxf(av.y + bv.y, 0.f), w2v.y, s);
            s = fmaf(fmaxf(av.z + bv.z, 0.f), w2v.z, s);
            s = fmaf(fmaxf(av.w + bv.w, 0.f), w2v.w, s);
            a8[i] = s;
        }
        __syncthreads();
    }
    const float b2v = b2p[0];
    #pragma unroll
    for (int i = 0; i < 8; ++i)
        g_scores[ebase + id8[i]] = a8[i] + b2v;
}

// ---------------------------------------------------------------------------
// K3: bitonic argsort + outputs + SMEM mask + fused segment-sum. bofs added.
// ---------------------------------------------------------------------------
__global__ void __launch_bounds__(1024) k3_sort(const int* __restrict__ ei,
                                                const float* __restrict__ hmat,
                                                float* __restrict__ out,
                                                int bofs) {
    __shared__ unsigned long long sk[4096];
    __shared__ float smask[512];
    __shared__ float red[16][64];
    const int b = blockIdx.x + bofs, tid = threadIdx.x;

    if (tid < 512) smask[tid] = 0.f;

    unsigned long long key[4];
    float4 sc = *(const float4*)(g_scores + b * EPB + tid * 4);
    float sv[4] = {sc.x, sc.y, sc.z, sc.w};
    #pragma unroll
    for (int r = 0; r < 4; ++r) {
        unsigned int u = __float_as_uint(sv[r]);
        unsigned int enc = (u & 0x80000000u) ? ~u : (u | 0x80000000u);
        key[r] = ((unsigned long long)(~enc) << 32) | (unsigned int)(tid * 4 + r);
    }

    for (int k = 2; k <= 4096; k <<= 1) {
        int j = k >> 1;
        for (; j >= 128; j >>= 1) {
            #pragma unroll
            for (int r = 0; r < 4; ++r) sk[tid * 4 + r] = key[r];
            __syncthreads();
            #pragma unroll
            for (int r = 0; r < 4; ++r) {
                int i = tid * 4 + r;
                unsigned long long pk = sk[i ^ j];
                bool up = ((i & k) == 0);
                bool lo = ((i & j) == 0);
                unsigned long long mn = key[r] < pk ? key[r] : pk;
                unsigned long long mx = key[r] < pk ? pk : key[r];
                key[r] = (lo == up) ? mn : mx;
            }
            __syncthreads();
        }
        for (; j >= 4; j >>= 1) {
            int lm = j >> 2;
            #pragma unroll
            for (int r = 0; r < 4; ++r) {
                unsigned long long pk = __shfl_xor_sync(0xffffffffu, key[r], lm);
                int i = tid * 4 + r;
                bool up = ((i & k) == 0);
                bool lo = ((i & j) == 0);
                unsigned long long mn = key[r] < pk ? key[r] : pk;
                unsigned long long mx = key[r] < pk ? pk : key[r];
                key[r] = (lo == up) ? mn : mx;
            }
        }
        if (k >= 4) {
            #pragma unroll
            for (int r = 0; r < 2; ++r) {
                int i = tid * 4 + r;
                bool up = ((i & k) == 0);
                unsigned long long a = key[r], c2 = key[r + 2];
                unsigned long long mn = a < c2 ? a : c2;
                unsigned long long mx = a < c2 ? c2 : a;
                key[r]     = up ? mn : mx;
                key[r + 2] = up ? mx : mn;
            }
        }
        #pragma unroll
        for (int p = 0; p < 2; ++p) {
            int r0 = p * 2;
            int i = tid * 4 + r0;
            bool up = ((i & k) == 0);
            unsigned long long a = key[r0], c2 = key[r0 + 1];
            unsigned long long mn = a < c2 ? a : c2;
            unsigned long long mx = a < c2 ? c2 : a;
            key[r0]     = up ? mn : mx;
            key[r0 + 1] = up ? mx : mn;
        }
    }

    const int ok = BNUM * DHID;
    const int os = ok + BNUM * KKEEP;
    #pragma unroll
    for (int r = 0; r < 4; ++r) {
        int pos = tid * 4 + r;
        unsigned long long kv = key[r];
        unsigned int enc = ~(unsigned int)(kv >> 32);
        unsigned int bits = (enc & 0x80000000u) ? (enc ^ 0x80000000u) : ~enc;
        float s = __uint_as_float(bits);
        int idx = (int)(unsigned int)(kv & 0xFFFFFFFFu);
        if (pos < KKEEP) {
            out[ok + b * KKEEP + pos] = s;
            int g = b * EPB + idx;
            smask[ei[g]         - b * NPB] = 1.f;
            smask[ei[E_TOT + g] - b * NPB] = 1.f;
        } else {
            out[os + b * KDROP + (pos - KKEEP)] = -s;
        }
    }
    __syncthreads();

    const int d = tid & 63, q = tid >> 6;
    const size_t nb = (size_t)b * NPB;
    float s = 0.f;
    #pragma unroll 8
    for (int n = q; n < NPB; n += 16)
        s = fmaf(smask[n], hmat[(nb + n) * 64 + d], s);
    red[q][d] = s;
    __syncthreads();
    if (tid < 64) {
        float t = 0.f;
        #pragma unroll
        for (int qq = 0; qq < 16; ++qq) t += red[qq][tid];
        out[b * 64 + tid] = t;
    }
}

// ---------------------------------------------------------------------------
extern "C" void kernel_launch(void* const* d_in, const int* in_sizes, int n_in,
                              void* d_out, int out_size) {
    const float* hmat = (const float*)d_in[0];
    const float* W1   = (const float*)d_in[1];
    const float* b1   = (const float*)d_in[2];
    const float* W2   = (const float*)d_in[3];
    const float* b2   = (const float*)d_in[4];
    const int*   ei   = (const int*)  d_in[5];
    float* out = (float*)d_out;

    const int smem1 = (64 * 256 + 64 * 68) * 4;        // 82944 B
    const int smem2 = (4 * 2 * 2048 + 256) * 4;        // 66560 B
    cudaFuncSetAttribute(k1_gemm, cudaFuncAttributeMaxDynamicSharedMemorySize, smem1);
    cudaFuncSetAttribute(k2_edges, cudaFuncAttributeMaxDynamicSharedMemorySize, smem2);

    // fork side streams from the capture-origin (legacy) stream
    cudaEventRecord(evOrigin, 0);
    cudaStreamWaitEvent(sA, evOrigin, 0);
    cudaStreamWaitEvent(sB, evOrigin, 0);
    cudaStreamWaitEvent(sC, evOrigin, 0);

    for (int g = 0; g < NGRP; ++g) {
        // k1: tiles for batches [g*BPG, (g+1)*BPG): BPG*8 tiles, x2 halves
        k1_gemm<<<BPG * 8 * 2, 256, smem1, sA>>>(hmat, W1, b1, g * BPG * 8);
        cudaEventRecord(evA[g], sA);

        cudaStreamWaitEvent(sB, evA[g], 0);
        k2_edges<<<BPG, 512, smem2, sB>>>(W2, b2, ei, g * BPG);
        cudaEventRecord(evB[g], sB);

        cudaStreamWaitEvent(sC, evB[g], 0);
        k3_sort<<<BPG, 1024, 0, sC>>>(ei, hmat, out, g * BPG);
    }
    cudaEventRecord(evLast, sC);
    cudaStreamWaitEvent(0, evLast, 0);   // join back into the origin stream
}

// round 16
// speedup vs baseline: 1.5834x; 1.5834x over previous
#include <cuda_runtime.h>
#include <cstdint>

#define E_TOT  (256*4096)
#define NNODE  (256*512)
#define DHID   64
#define BNUM   256
#define EPB    4096
#define NPB    512
#define KKEEP  1024
#define KDROP  3072

// chunk-major AB: [batch][chunk 0..127][node 0..511] float4
__device__ float g_AB[(size_t)BNUM * 128 * 512 * 4];
__device__ float g_scores[E_TOT];

__device__ __forceinline__ unsigned long long pk2(float x, float y) {
    unsigned long long r;
    asm("mov.b64 %0, {%1, %2};" : "=l"(r) : "f"(x), "f"(y));
    return r;
}
__device__ __forceinline__ void fma2(unsigned long long& d,
                                     unsigned long long a, unsigned long long b) {
    asm("fma.rn.f32x2 %0, %1, %2, %0;" : "+l"(d) : "l"(a), "l"(b));
}
__device__ __forceinline__ void cp16(unsigned int s, const void* g) {
    asm volatile("cp.async.cg.shared.global [%0], [%1], 16;" :: "r"(s), "l"(g));
}

// ---------------------------------------------------------------------------
// K1: AB = h @ Wc (R7 core, b1 folded in epilogue copy). Empirical best.
// ---------------------------------------------------------------------------
__global__ void __launch_bounds__(256, 2) k1_gemm(const float* __restrict__ hmat,
                                                  const float* __restrict__ W1,
                                                  const float* __restrict__ b1) {
    extern __shared__ float sm1[];
    __shared__ float b1s[256];
    float* Ws = sm1;              // [64][256]
    float* hs = sm1 + 64 * 256;   // [64][68]
    const int tid  = threadIdx.x;
    const int tile = blockIdx.x >> 1;
    const int half = blockIdx.x & 1;
    const int rowbase = tile * 64;
    const int b     = rowbase >> 9;
    const int nboff = rowbase & 511;

    if (tid < 64) *(float4*)(b1s + tid * 4) = *(const float4*)(b1 + tid * 4);
    #pragma unroll
    for (int j = 0; j < 16; ++j) {
        int i = tid + j * 256;
        int k = i >> 6, o4 = i & 63;
        *(float4*)(Ws + k * 256 + o4 * 4) =
            *(const float4*)(W1 + (size_t)(half * 64 + k) * 256 + o4 * 4);
    }
    #pragma unroll
    for (int j = 0; j < 4; ++j) {
        int i = tid + j * 256;
        int n = i >> 4, k4 = i & 15;
        float4 v = *(const float4*)(hmat + (size_t)(rowbase + n) * 64 + k4 * 4);
        hs[(k4 * 4 + 0) * 68 + n] = v.x;
        hs[(k4 * 4 + 1) * 68 + n] = v.y;
        hs[(k4 * 4 + 2) * 68 + n] = v.z;
        hs[(k4 * 4 + 3) * 68 + n] = v.w;
    }
    __syncthreads();

    const int w = tid >> 5, l = tid & 31;
    const int r0 = w * 8;

    unsigned long long acc[8][4];
    #pragma unroll
    for (int i = 0; i < 8; ++i)
        #pragma unroll
        for (int p = 0; p < 4; ++p) acc[i][p] = 0ull;

    #pragma unroll 4
    for (int k = 0; k < 64; ++k) {
        float4 h0 = *(const float4*)(hs + k * 68 + r0);
        float4 h1 = *(const float4*)(hs + k * 68 + r0 + 4);
        ulonglong2 w0 = *(const ulonglong2*)(Ws + k * 256 + 4 * l);
        ulonglong2 w1 = *(const ulonglong2*)(Ws + k * 256 + 128 + 4 * l);
        float hv[8] = {h0.x, h0.y, h0.z, h0.w, h1.x, h1.y, h1.z, h1.w};
        #pragma unroll
        for (int i = 0; i < 8; ++i) {
            unsigned long long a2 = pk2(hv[i], hv[i]);
            fma2(acc[i][0], a2, w0.x); fma2(acc[i][1], a2, w0.y);
            fma2(acc[i][2], a2, w1.x); fma2(acc[i][3], a2, w1.y);
        }
    }

    __syncthreads();
    float4* st = (float4*)sm1;
    #pragma unroll
    for (int i = 0; i < 8; ++i) {
        int node = r0 + i;
        float4 v0, v1;
        *(unsigned long long*)&v0.x = acc[i][0];
        *(unsigned long long*)&v0.z = acc[i][1];
        *(unsigned long long*)&v1.x = acc[i][2];
        *(unsigned long long*)&v1.z = acc[i][3];
        st[l * 65 + node]        = v0;
        st[(32 + l) * 65 + node] = v1;
    }
    __syncthreads();
    float4* dst = (float4*)g_AB;
    if (half == 0) {
        #pragma unroll
        for (int j = 0; j < 16; ++j) {
            int idx = tid + j * 256;
            int cc = idx >> 6, node = idx & 63;
            float4 v = st[cc * 65 + node];
            float4 bv = *(const float4*)(b1s + cc * 4);
            v.x += bv.x; v.y += bv.y; v.z += bv.z; v.w += bv.w;
            dst[((size_t)b * 128 + cc) * 512 + nboff + node] = v;
        }
    } else {
        #pragma unroll
        for (int j = 0; j < 16; ++j) {
            int idx = tid + j * 256;
            int cc = idx >> 6, node = idx & 63;
            dst[((size_t)b * 128 + 64 + cc) * 512 + nboff + node] = st[cc * 65 + node];
        }
    }
}

// ---------------------------------------------------------------------------
// K2: edge scores, ONE CTA per batch, 8 sorted edges/thread, cp.async depth-3.
// Single barrier per chunk (cp issue is after the post-wait barrier, which
// already proves the overwritten buffer was fully consumed).
// ---------------------------------------------------------------------------
__global__ void __launch_bounds__(512, 2) k2_edges(const float* __restrict__ W2,
                                                   const float* __restrict__ b2p,
                                                   const int*   __restrict__ ei) {
    extern __shared__ float sm2[];
    float* stage = sm2;                 // [4 bufs][2 sides][2048] = 64 KB
    float* w2s   = sm2 + 4 * 2 * 2048;  // [256]
    int* scnt  = (int*)sm2;             // [512]
    int* wsumS = (int*)sm2 + 512;       // [16]
    int* ssrow = (int*)sm2 + 544;       // [4096]
    int* sscol = ssrow + 4096;
    int* ssid  = sscol + 4096;

    const int tid = threadIdx.x;
    const int b   = blockIdx.x;
    const int ebase = b * EPB;

    scnt[tid] = 0;
    __syncthreads();
    int r8l[8], c8l[8];
    #pragma unroll
    for (int i = 0; i < 8; ++i) {
        int j = tid + i * 512;
        r8l[i] = ei[ebase + j]         - b * NPB;
        c8l[i] = ei[E_TOT + ebase + j] - b * NPB;
        atomicAdd(&scnt[r8l[i]], 1);
    }
    __syncthreads();
    {
        const int lane = tid & 31, wd = tid >> 5;
        int v = scnt[tid];
        int x = v;
        #pragma unroll
        for (int o = 1; o < 32; o <<= 1) {
            int y = __shfl_up_sync(0xffffffffu, x, o);
            if (lane >= o) x += y;
        }
        if (lane == 31) wsumS[wd] = x;
        __syncthreads();
        if (tid < 16) {
            int y = wsumS[tid], z = y;
            #pragma unroll
            for (int o = 1; o < 16; o <<= 1) {
                int t = __shfl_up_sync(0xffffu, z, o);
                if (tid >= o) z += t;
            }
            wsumS[tid] = z - y;
        }
        __syncthreads();
        int excl = x - v + wsumS[wd];
        __syncthreads();
        scnt[tid] = excl;
        __syncthreads();
    }
    #pragma unroll
    for (int i = 0; i < 8; ++i) {
        int p = atomicAdd(&scnt[r8l[i]], 1);
        ssrow[p] = r8l[i];
        sscol[p] = c8l[i];
        ssid [p] = tid + i * 512;
    }
    __syncthreads();
    int ro[8], co[8], id8[8];
    {
        int4 ra = *(const int4*)(ssrow + tid * 8);
        int4 rb = *(const int4*)(ssrow + tid * 8 + 4);
        int4 ca = *(const int4*)(sscol + tid * 8);
        int4 cb = *(const int4*)(sscol + tid * 8 + 4);
        int4 ia = *(const int4*)(ssid + tid * 8);
        int4 ib = *(const int4*)(ssid + tid * 8 + 4);
        ro[0]=ra.x*4; ro[1]=ra.y*4; ro[2]=ra.z*4; ro[3]=ra.w*4;
        ro[4]=rb.x*4; ro[5]=rb.y*4; ro[6]=rb.z*4; ro[7]=rb.w*4;
        co[0]=ca.x*4; co[1]=ca.y*4; co[2]=ca.z*4; co[3]=ca.w*4;
        co[4]=cb.x*4; co[5]=cb.y*4; co[6]=cb.z*4; co[7]=cb.w*4;
        id8[0]=ia.x; id8[1]=ia.y; id8[2]=ia.z; id8[3]=ia.w;
        id8[4]=ib.x; id8[5]=ib.y; id8[6]=ib.z; id8[7]=ib.w;
    }
    __syncthreads();
    if (tid < 64) *(float4*)(w2s + tid * 4) = *(const float4*)(W2 + tid * 4);
    __syncthreads();

    float a8[8];
    #pragma unroll
    for (int i = 0; i < 8; ++i) a8[i] = 0.f;

    const float4* gA = (const float4*)g_AB + (size_t)b * 128 * 512;
    const unsigned int sb32 =
        (unsigned int)__cvta_generic_to_shared(stage) + tid * 16;

    #pragma unroll
    for (int p = 0; p < 3; ++p) {
        cp16(sb32 + (p * 2)     * 2048 * 4, gA + (size_t)p        * 512 + tid);
        cp16(sb32 + (p * 2 + 1) * 2048 * 4, gA + (size_t)(64 + p) * 512 + tid);
        asm volatile("cp.async.commit_group;");
    }

    for (int c = 0; c < 64; ++c) {
        if (c < 62)       asm volatile("cp.async.wait_group 2;");
        else if (c == 62) asm volatile("cp.async.wait_group 1;");
        else              asm volatile("cp.async.wait_group 0;");
        __syncthreads();   // data visible; prior-iter consumption proven done

        const int nc = c + 3;
        if (nc < 64) {
            const int nb = nc & 3;
            cp16(sb32 + (nb * 2)     * 2048 * 4, gA + (size_t)nc        * 512 + tid);
            cp16(sb32 + (nb * 2 + 1) * 2048 * 4, gA + (size_t)(64 + nc) * 512 + tid);
            asm volatile("cp.async.commit_group;");
        }

        const int buf = c & 3;
        const float* A0 = stage + (buf * 2) * 2048;
        const float* B0 = stage + (buf * 2 + 1) * 2048;
        const float4 w2v = *(const float4*)(w2s + c * 4);

        float4 av = *(const float4*)(A0 + ro[0]);
        #pragma unroll
        for (int i = 0; i < 8; ++i) {
            if (i > 0 && ro[i] != ro[i - 1]) av = *(const float4*)(A0 + ro[i]);
            float4 bv = *(const float4*)(B0 + co[i]);
            float s = a8[i];
            s = fmaf(fmaxf(av.x + bv.x, 0.f), w2v.x, s);
            s = fmaf(fmaxf(av.y + bv.y, 0.f), w2v.y, s);
            s = fmaf(fmaxf(av.z + bv.z, 0.f), w2v.z, s);
            s = fmaf(fmaxf(av.w + bv.w, 0.f), w2v.w, s);
            a8[i] = s;
        }
        // no trailing barrier: next iter's post-wait barrier covers buffer reuse
    }
    const float b2v = b2p[0];
    #pragma unroll
    for (int i = 0; i < 8; ++i)
        g_scores[ebase + id8[i]] = a8[i] + b2v;
}

// ---------------------------------------------------------------------------
// K3: bitonic argsort, 512 threads x 8 keys (10 SMEM stages, 5 shfl, 3 local)
// + outputs + SMEM mask + fused segment-sum.
// ---------------------------------------------------------------------------
__global__ void __launch_bounds__(512) k3_sort(const int* __restrict__ ei,
                                               const float* __restrict__ hmat,
                                               float* __restrict__ out) {
    __shared__ unsigned long long sk[4096];
    __shared__ float smask[512];
    __shared__ float red[8][64];
    const int b = blockIdx.x, tid = threadIdx.x;

    smask[tid] = 0.f;

    unsigned long long key[8];
    {
        float4 s0 = *(const float4*)(g_scores + b * EPB + tid * 8);
        float4 s1 = *(const float4*)(g_scores + b * EPB + tid * 8 + 4);
        float sv[8] = {s0.x, s0.y, s0.z, s0.w, s1.x, s1.y, s1.z, s1.w};
        #pragma unroll
        for (int r = 0; r < 8; ++r) {
            unsigned int u = __float_as_uint(sv[r]);
            unsigned int enc = (u & 0x80000000u) ? ~u : (u | 0x80000000u);
            key[r] = ((unsigned long long)(~enc) << 32) | (unsigned int)(tid * 8 + r);
        }
    }

    for (int k = 2; k <= 4096; k <<= 1) {
        int j = k >> 1;
        for (; j >= 256; j >>= 1) {          // cross-warp via SMEM
            #pragma unroll
            for (int r = 0; r < 8; ++r) sk[tid * 8 + r] = key[r];
            __syncthreads();
            #pragma unroll
            for (int r = 0; r < 8; ++r) {
                int i = tid * 8 + r;
                unsigned long long pk = sk[i ^ j];
                bool up = ((i & k) == 0);
                bool lo = ((i & j) == 0);
                unsigned long long mn = key[r] < pk ? key[r] : pk;
                unsigned long long mx = key[r] < pk ? pk : key[r];
                key[r] = (lo == up) ? mn : mx;
            }
            __syncthreads();
        }
        for (; j >= 8; j >>= 1) {            // intra-warp via shfl
            int lm = j >> 3;
            #pragma unroll
            for (int r = 0; r < 8; ++r) {
                unsigned long long pk = __shfl_xor_sync(0xffffffffu, key[r], lm);
                int i = tid * 8 + r;
                bool up = ((i & k) == 0);
                bool lo = ((i & j) == 0);
                unsigned long long mn = key[r] < pk ? key[r] : pk;
                unsigned long long mx = key[r] < pk ? pk : key[r];
                key[r] = (lo == up) ? mn : mx;
            }
        }
        for (; j >= 1; j >>= 1) {            // in-thread (j = 4,2,1)
            #pragma unroll
            for (int r = 0; r < 8; ++r) {
                if ((r & j) == 0) {
                    int p = r | j;
                    int i = tid * 8 + r;
                    bool up = ((i & k) == 0);
                    unsigned long long a = key[r], c2 = key[p];
                    unsigned long long mn = a < c2 ? a : c2;
                    unsigned long long mx = a < c2 ? c2 : a;
                    key[r] = up ? mn : mx;
                    key[p] = up ? mx : mn;
                }
            }
        }
    }

    const int ok = BNUM * DHID;
    const int os = ok + BNUM * KKEEP;
    #pragma unroll
    for (int r = 0; r < 8; ++r) {
        int pos = tid * 8 + r;
        unsigned long long kv = key[r];
        unsigned int enc = ~(unsigned int)(kv >> 32);
        unsigned int bits = (enc & 0x80000000u) ? (enc ^ 0x80000000u) : ~enc;
        float s = __uint_as_float(bits);
        int idx = (int)(unsigned int)(kv & 0xFFFFFFFFu);
        if (pos < KKEEP) {
            out[ok + b * KKEEP + pos] = s;
            int g = b * EPB + idx;
            smask[ei[g]         - b * NPB] = 1.f;
            smask[ei[E_TOT + g] - b * NPB] = 1.f;
        } else {
            out[os + b * KDROP + (pos - KKEEP)] = -s;
        }
    }
    __syncthreads();

    // fused segment-sum (512 threads: q = 0..7)
    const int d = tid & 63, q = tid >> 6;
    const size_t nb = (size_t)b * NPB;
    float s0 = 0.f, s1 = 0.f;
    #pragma unroll 4
    for (int n = q; n < NPB; n += 16) {
        s0 = fmaf(smask[n],     hmat[(nb + n) * 64 + d],     s0);
        s1 = fmaf(smask[n + 8], hmat[(nb + n + 8) * 64 + d], s1);
    }
    red[q][d] = s0 + s1;
    __syncthreads();
    if (tid < 64) {
        float t = 0.f;
        #pragma unroll
        for (int qq = 0; qq < 8; ++qq) t += red[qq][tid];
        out[b * 64 + tid] = t;
    }
}

// ---------------------------------------------------------------------------
extern "C" void kernel_launch(void* const* d_in, const int* in_sizes, int n_in,
                              void* d_out, int out_size) {
    const float* hmat = (const float*)d_in[0];
    const float* W1   = (const float*)d_in[1];
    const float* b1   = (const float*)d_in[2];
    const float* W2   = (const float*)d_in[3];
    const float* b2   = (const float*)d_in[4];
    const int*   ei   = (const int*)  d_in[5];
    float* out = (float*)d_out;

    const int smem1 = (64 * 256 + 64 * 68) * 4;        // 82944 B
    const int smem2 = (4 * 2 * 2048 + 256) * 4;        // 66560 B
    cudaFuncSetAttribute(k1_gemm, cudaFuncAttributeMaxDynamicSharedMemorySize, smem1);
    cudaFuncSetAttribute(k2_edges, cudaFuncAttributeMaxDynamicSharedMemorySize, smem2);

    k1_gemm<<<4096, 256, smem1>>>(hmat, W1, b1);
    k2_edges<<<BNUM, 512, smem2>>>(W2, b2, ei);
    k3_sort<<<BNUM, 512>>>(ei, hmat, out);
}

// round 17
// speedup vs baseline: 1.7889x; 1.1298x over previous
#include <cuda_runtime.h>
#include <cstdint>

#define E_TOT  (256*4096)
#define NNODE  (256*512)
#define DHID   64
#define BNUM   256
#define EPB    4096
#define NPB    512
#define KKEEP  1024
#define KDROP  3072

// chunk-major AB: [batch][chunk 0..127][node 0..511] float4
__device__ float g_AB[(size_t)BNUM * 128 * 512 * 4];
__device__ float g_scores[E_TOT];

__device__ __forceinline__ unsigned long long pk2(float x, float y) {
    unsigned long long r;
    asm("mov.b64 %0, {%1, %2};" : "=l"(r) : "f"(x), "f"(y));
    return r;
}
__device__ __forceinline__ void fma2(unsigned long long& d,
                                     unsigned long long a, unsigned long long b) {
    asm("fma.rn.f32x2 %0, %1, %2, %0;" : "+l"(d) : "l"(a), "l"(b));
}
__device__ __forceinline__ void cp16(unsigned int s, const void* g) {
    asm volatile("cp.async.cg.shared.global [%0], [%1], 16;" :: "r"(s), "l"(g));
}

// ---------------------------------------------------------------------------
// K1: AB = h @ Wc (R7 core, b1 folded in epilogue copy). Empirical best.
// ---------------------------------------------------------------------------
__global__ void __launch_bounds__(256, 2) k1_gemm(const float* __restrict__ hmat,
                                                  const float* __restrict__ W1,
                                                  const float* __restrict__ b1) {
    extern __shared__ float sm1[];
    __shared__ float b1s[256];
    float* Ws = sm1;              // [64][256]
    float* hs = sm1 + 64 * 256;   // [64][68]
    const int tid  = threadIdx.x;
    const int tile = blockIdx.x >> 1;
    const int half = blockIdx.x & 1;
    const int rowbase = tile * 64;
    const int b     = rowbase >> 9;
    const int nboff = rowbase & 511;

    if (tid < 64) *(float4*)(b1s + tid * 4) = *(const float4*)(b1 + tid * 4);
    #pragma unroll
    for (int j = 0; j < 16; ++j) {
        int i = tid + j * 256;
        int k = i >> 6, o4 = i & 63;
        *(float4*)(Ws + k * 256 + o4 * 4) =
            *(const float4*)(W1 + (size_t)(half * 64 + k) * 256 + o4 * 4);
    }
    #pragma unroll
    for (int j = 0; j < 4; ++j) {
        int i = tid + j * 256;
        int n = i >> 4, k4 = i & 15;
        float4 v = *(const float4*)(hmat + (size_t)(rowbase + n) * 64 + k4 * 4);
        hs[(k4 * 4 + 0) * 68 + n] = v.x;
        hs[(k4 * 4 + 1) * 68 + n] = v.y;
        hs[(k4 * 4 + 2) * 68 + n] = v.z;
        hs[(k4 * 4 + 3) * 68 + n] = v.w;
    }
    __syncthreads();

    const int w = tid >> 5, l = tid & 31;
    const int r0 = w * 8;

    unsigned long long acc[8][4];
    #pragma unroll
    for (int i = 0; i < 8; ++i)
        #pragma unroll
        for (int p = 0; p < 4; ++p) acc[i][p] = 0ull;

    #pragma unroll 4
    for (int k = 0; k < 64; ++k) {
        float4 h0 = *(const float4*)(hs + k * 68 + r0);
        float4 h1 = *(const float4*)(hs + k * 68 + r0 + 4);
        ulonglong2 w0 = *(const ulonglong2*)(Ws + k * 256 + 4 * l);
        ulonglong2 w1 = *(const ulonglong2*)(Ws + k * 256 + 128 + 4 * l);
        float hv[8] = {h0.x, h0.y, h0.z, h0.w, h1.x, h1.y, h1.z, h1.w};
        #pragma unroll
        for (int i = 0; i < 8; ++i) {
            unsigned long long a2 = pk2(hv[i], hv[i]);
            fma2(acc[i][0], a2, w0.x); fma2(acc[i][1], a2, w0.y);
            fma2(acc[i][2], a2, w1.x); fma2(acc[i][3], a2, w1.y);
        }
    }

    __syncthreads();
    float4* st = (float4*)sm1;
    #pragma unroll
    for (int i = 0; i < 8; ++i) {
        int node = r0 + i;
        float4 v0, v1;
        *(unsigned long long*)&v0.x = acc[i][0];
        *(unsigned long long*)&v0.z = acc[i][1];
        *(unsigned long long*)&v1.x = acc[i][2];
        *(unsigned long long*)&v1.z = acc[i][3];
        st[l * 65 + node]        = v0;
        st[(32 + l) * 65 + node] = v1;
    }
    __syncthreads();
    float4* dst = (float4*)g_AB;
    if (half == 0) {
        #pragma unroll
        for (int j = 0; j < 16; ++j) {
            int idx = tid + j * 256;
            int cc = idx >> 6, node = idx & 63;
            float4 v = st[cc * 65 + node];
            float4 bv = *(const float4*)(b1s + cc * 4);
            v.x += bv.x; v.y += bv.y; v.z += bv.z; v.w += bv.w;
            dst[((size_t)b * 128 + cc) * 512 + nboff + node] = v;
        }
    } else {
        #pragma unroll
        for (int j = 0; j < 16; ++j) {
            int idx = tid + j * 256;
            int cc = idx >> 6, node = idx & 63;
            dst[((size_t)b * 128 + 64 + cc) * 512 + nboff + node] = st[cc * 65 + node];
        }
    }
}

// ---------------------------------------------------------------------------
// K2: edge scores, ONE CTA per batch (exact R14 version — empirical best).
// ---------------------------------------------------------------------------
__global__ void __launch_bounds__(512, 2) k2_edges(const float* __restrict__ W2,
                                                   const float* __restrict__ b2p,
                                                   const int*   __restrict__ ei) {
    extern __shared__ float sm2[];
    float* stage = sm2;                 // [4 bufs][2 sides][2048] = 64 KB
    float* w2s   = sm2 + 4 * 2 * 2048;  // [256]
    int* scnt  = (int*)sm2;             // [512]
    int* wsumS = (int*)sm2 + 512;       // [16]
    int* ssrow = (int*)sm2 + 544;       // [4096]
    int* sscol = ssrow + 4096;
    int* ssid  = sscol + 4096;

    const int tid = threadIdx.x;
    const int b   = blockIdx.x;
    const int ebase = b * EPB;

    scnt[tid] = 0;
    __syncthreads();
    int r8l[8], c8l[8];
    #pragma unroll
    for (int i = 0; i < 8; ++i) {
        int j = tid + i * 512;
        r8l[i] = ei[ebase + j]         - b * NPB;
        c8l[i] = ei[E_TOT + ebase + j] - b * NPB;
        atomicAdd(&scnt[r8l[i]], 1);
    }
    __syncthreads();
    {
        const int lane = tid & 31, wd = tid >> 5;
        int v = scnt[tid];
        int x = v;
        #pragma unroll
        for (int o = 1; o < 32; o <<= 1) {
            int y = __shfl_up_sync(0xffffffffu, x, o);
            if (lane >= o) x += y;
        }
        if (lane == 31) wsumS[wd] = x;
        __syncthreads();
        if (tid < 16) {
            int y = wsumS[tid], z = y;
            #pragma unroll
            for (int o = 1; o < 16; o <<= 1) {
                int t = __shfl_up_sync(0xffffu, z, o);
                if (tid >= o) z += t;
            }
            wsumS[tid] = z - y;
        }
        __syncthreads();
        int excl = x - v + wsumS[wd];
        __syncthreads();
        scnt[tid] = excl;
        __syncthreads();
    }
    #pragma unroll
    for (int i = 0; i < 8; ++i) {
        int p = atomicAdd(&scnt[r8l[i]], 1);
        ssrow[p] = r8l[i];
        sscol[p] = c8l[i];
        ssid [p] = tid + i * 512;
    }
    __syncthreads();
    int ro[8], co[8], id8[8];
    {
        int4 ra = *(const int4*)(ssrow + tid * 8);
        int4 rb = *(const int4*)(ssrow + tid * 8 + 4);
        int4 ca = *(const int4*)(sscol + tid * 8);
        int4 cb = *(const int4*)(sscol + tid * 8 + 4);
        int4 ia = *(const int4*)(ssid + tid * 8);
        int4 ib = *(const int4*)(ssid + tid * 8 + 4);
        ro[0]=ra.x*4; ro[1]=ra.y*4; ro[2]=ra.z*4; ro[3]=ra.w*4;
        ro[4]=rb.x*4; ro[5]=rb.y*4; ro[6]=rb.z*4; ro[7]=rb.w*4;
        co[0]=ca.x*4; co[1]=ca.y*4; co[2]=ca.z*4; co[3]=ca.w*4;
        co[4]=cb.x*4; co[5]=cb.y*4; co[6]=cb.z*4; co[7]=cb.w*4;
        id8[0]=ia.x; id8[1]=ia.y; id8[2]=ia.z; id8[3]=ia.w;
        id8[4]=ib.x; id8[5]=ib.y; id8[6]=ib.z; id8[7]=ib.w;
    }
    __syncthreads();
    if (tid < 64) *(float4*)(w2s + tid * 4) = *(const float4*)(W2 + tid * 4);
    __syncthreads();

    float a8[8];
    #pragma unroll
    for (int i = 0; i < 8; ++i) a8[i] = 0.f;

    const float4* gA = (const float4*)g_AB + (size_t)b * 128 * 512;
    const unsigned int sb32 =
        (unsigned int)__cvta_generic_to_shared(stage) + tid * 16;

    #pragma unroll
    for (int p = 0; p < 3; ++p) {
        cp16(sb32 + (p * 2)     * 2048 * 4, gA + (size_t)p        * 512 + tid);
        cp16(sb32 + (p * 2 + 1) * 2048 * 4, gA + (size_t)(64 + p) * 512 + tid);
        asm volatile("cp.async.commit_group;");
    }

    for (int c = 0; c < 64; ++c) {
        if (c < 62)       asm volatile("cp.async.wait_group 2;");
        else if (c == 62) asm volatile("cp.async.wait_group 1;");
        else              asm volatile("cp.async.wait_group 0;");
        __syncthreads();

        const int nc = c + 3;
        if (nc < 64) {
            const int nb = nc & 3;
            cp16(sb32 + (nb * 2)     * 2048 * 4, gA + (size_t)nc        * 512 + tid);
            cp16(sb32 + (nb * 2 + 1) * 2048 * 4, gA + (size_t)(64 + nc) * 512 + tid);
            asm volatile("cp.async.commit_group;");
        }

        const int buf = c & 3;
        const float* A0 = stage + (buf * 2) * 2048;
        const float* B0 = stage + (buf * 2 + 1) * 2048;
        const float4 w2v = *(const float4*)(w2s + c * 4);

        float4 av = *(const float4*)(A0 + ro[0]);
        #pragma unroll
        for (int i = 0; i < 8; ++i) {
            if (i > 0 && ro[i] != ro[i - 1]) av = *(const float4*)(A0 + ro[i]);
            float4 bv = *(const float4*)(B0 + co[i]);
            float s = a8[i];
            s = fmaf(fmaxf(av.x + bv.x, 0.f), w2v.x, s);
            s = fmaf(fmaxf(av.y + bv.y, 0.f), w2v.y, s);
            s = fmaf(fmaxf(av.z + bv.z, 0.f), w2v.z, s);
            s = fmaf(fmaxf(av.w + bv.w, 0.f), w2v.w, s);
            a8[i] = s;
        }
        __syncthreads();
    }
    const float b2v = b2p[0];
    #pragma unroll
    for (int i = 0; i < 8; ++i)
        g_scores[ebase + id8[i]] = a8[i] + b2v;
}

// ---------------------------------------------------------------------------
// K3: bitonic argsort (1024 thr x 4 keys, R14 structure) with VECTORIZED
// SMEM stages: partners at i^j are contiguous for j>=128, so use 16B ld/st.
// ---------------------------------------------------------------------------
__global__ void __launch_bounds__(1024) k3_sort(const int* __restrict__ ei,
                                                const float* __restrict__ hmat,
                                                float* __restrict__ out) {
    __shared__ unsigned long long sk[4096];
    __shared__ float smask[512];
    __shared__ float red[16][64];
    const int b = blockIdx.x, tid = threadIdx.x;

    if (tid < 512) smask[tid] = 0.f;

    unsigned long long key[4];
    float4 sc = *(const float4*)(g_scores + b * EPB + tid * 4);
    float sv[4] = {sc.x, sc.y, sc.z, sc.w};
    #pragma unroll
    for (int r = 0; r < 4; ++r) {
        unsigned int u = __float_as_uint(sv[r]);
        unsigned int enc = (u & 0x80000000u) ? ~u : (u | 0x80000000u);
        key[r] = ((unsigned long long)(~enc) << 32) | (unsigned int)(tid * 4 + r);
    }

    for (int k = 2; k <= 4096; k <<= 1) {
        int j = k >> 1;
        for (; j >= 128; j >>= 1) {
            // store 4 keys with 2x 16B STS
            {
                ulonglong2 v0; v0.x = key[0]; v0.y = key[1];
                ulonglong2 v1; v1.x = key[2]; v1.y = key[3];
                *(ulonglong2*)(sk + tid * 4)     = v0;
                *(ulonglong2*)(sk + tid * 4 + 2) = v1;
            }
            __syncthreads();
            // partners contiguous: base = (tid*4)^j  (j multiple of 4, r<4)
            {
                int base = (tid * 4) ^ j;
                ulonglong2 p0 = *(const ulonglong2*)(sk + base);
                ulonglong2 p1 = *(const ulonglong2*)(sk + base + 2);
                unsigned long long pks[4] = {p0.x, p0.y, p1.x, p1.y};
                #pragma unroll
                for (int r = 0; r < 4; ++r) {
                    int i = tid * 4 + r;
                    unsigned long long pk = pks[r];
                    bool up = ((i & k) == 0);
                    bool lo = ((i & j) == 0);
                    unsigned long long mn = key[r] < pk ? key[r] : pk;
                    unsigned long long mx = key[r] < pk ? pk : key[r];
                    key[r] = (lo == up) ? mn : mx;
                }
            }
            __syncthreads();
        }
        for (; j >= 4; j >>= 1) {
            int lm = j >> 2;
            #pragma unroll
            for (int r = 0; r < 4; ++r) {
                unsigned long long pk = __shfl_xor_sync(0xffffffffu, key[r], lm);
                int i = tid * 4 + r;
                bool up = ((i & k) == 0);
                bool lo = ((i & j) == 0);
                unsigned long long mn = key[r] < pk ? key[r] : pk;
                unsigned long long mx = key[r] < pk ? pk : key[r];
                key[r] = (lo == up) ? mn : mx;
            }
        }
        if (k >= 4) {
            #pragma unroll
            for (int r = 0; r < 2; ++r) {
                int i = tid * 4 + r;
                bool up = ((i & k) == 0);
                unsigned long long a = key[r], c2 = key[r + 2];
                unsigned long long mn = a < c2 ? a : c2;
                unsigned long long mx = a < c2 ? c2 : a;
                key[r]     = up ? mn : mx;
                key[r + 2] = up ? mx : mn;
            }
        }
        #pragma unroll
        for (int p = 0; p < 2; ++p) {
            int r0 = p * 2;
            int i = tid * 4 + r0;
            bool up = ((i & k) == 0);
            unsigned long long a = key[r0], c2 = key[r0 + 1];
            unsigned long long mn = a < c2 ? a : c2;
            unsigned long long mx = a < c2 ? c2 : a;
            key[r0]     = up ? mn : mx;
            key[r0 + 1] = up ? mx : mn;
        }
    }

    const int ok = BNUM * DHID;
    const int os = ok + BNUM * KKEEP;
    #pragma unroll
    for (int r = 0; r < 4; ++r) {
        int pos = tid * 4 + r;
        unsigned long long kv = key[r];
        unsigned int enc = ~(unsigned int)(kv >> 32);
        unsigned int bits = (enc & 0x80000000u) ? (enc ^ 0x80000000u) : ~enc;
        float s = __uint_as_float(bits);
        int idx = (int)(unsigned int)(kv & 0xFFFFFFFFu);
        if (pos < KKEEP) {
            out[ok + b * KKEEP + pos] = s;
            int g = b * EPB + idx;
            smask[ei[g]         - b * NPB] = 1.f;
            smask[ei[E_TOT + g] - b * NPB] = 1.f;
        } else {
            out[os + b * KDROP + (pos - KKEEP)] = -s;
        }
    }
    __syncthreads();

    const int d = tid & 63, q = tid >> 6;
    const size_t nb = (size_t)b * NPB;
    float s = 0.f;
    #pragma unroll 8
    for (int n = q; n < NPB; n += 16)
        s = fmaf(smask[n], hmat[(nb + n) * 64 + d], s);
    red[q][d] = s;
    __syncthreads();
    if (tid < 64) {
        float t = 0.f;
        #pragma unroll
        for (int qq = 0; qq < 16; ++qq) t += red[qq][tid];
        out[b * 64 + tid] = t;
    }
}

// ---------------------------------------------------------------------------
extern "C" void kernel_launch(void* const* d_in, const int* in_sizes, int n_in,
                              void* d_out, int out_size) {
    const float* hmat = (const float*)d_in[0];
    const float* W1   = (const float*)d_in[1];
    const float* b1   = (const float*)d_in[2];
    const float* W2   = (const float*)d_in[3];
    const float* b2   = (const float*)d_in[4];
    const int*   ei   = (const int*)  d_in[5];
    float* out = (float*)d_out;

    const int smem1 = (64 * 256 + 64 * 68) * 4;        // 82944 B
    const int smem2 = (4 * 2 * 2048 + 256) * 4;        // 66560 B
    cudaFuncSetAttribute(k1_gemm, cudaFuncAttributeMaxDynamicSharedMemorySize, smem1);
    cudaFuncSetAttribute(k2_edges, cudaFuncAttributeMaxDynamicSharedMemorySize, smem2);

    k1_gemm<<<4096, 256, smem1>>>(hmat, W1, b1);
    k2_edges<<<BNUM, 512, smem2>>>(W2, b2, ei);
    k3_sort<<<BNUM, 1024>>>(ei, hmat, out);
}